// round 15
// baseline (speedup 1.0000x reference)
#include <cuda_runtime.h>
#include <cuda_bf16.h>
#include <cuda_fp16.h>
#include <cstdint>
#include <math.h>

#define GFD   4096
#define DH    1024
#define BATCH 32
#define TK    196
#define BT    (BATCH * TK)   // 6272

// Output layout in d_out (float): c_img[32,1024] | coverage_new[32,196,1] | alpha[32,196,1]
#define OUT_C      0
#define OUT_COV    (BATCH * DH)
#define OUT_ALPHA  (BATCH * DH + BT)

// ============================ scratch (__device__ globals) ============================
__device__ __align__(1024) __half g_WgF[GFD * GFD];    // Wg fp16 [GFD, GFD] row-major (K contiguous)
__device__ __align__(1024) __half g_GsTF[DH * GFD];    // Gs^T fp16 single [DH, GFD]
__device__ __align__(1024) __half g_W2TF[DH * GFD];    // W2^T fp16 single [DH, GFD]
__device__ __align__(1024) __half g_gfF[BT * GFD];     // gf fp16 single
__device__ __align__(1024) __half g_WgsTF[DH * DH];    // Wgs^T fp16 single [DH, DH]
__device__ __align__(1024) __half g_gsH[BT * DH];      // g_star fp16 hi
__device__ __align__(1024) __half g_gsL[BT * DH];      // g_star fp16 lo (cimg only)
__device__ float g_b2[DH];
__device__ float g_dec[BATCH * DH];
__device__ float g_scores[BT];
__device__ float g_alpha[BT];

// ============================ helpers ============================
__device__ __forceinline__ uint32_t smem_u32(const void* p) {
    uint32_t a;
    asm("{ .reg .u64 t; cvta.to.shared.u64 t, %1; cvt.u32.u64 %0, t; }" : "=r"(a) : "l"(p));
    return a;
}
__device__ __forceinline__ void ldsm4(uint32_t* r, uint32_t addr) {
    asm volatile("ldmatrix.sync.aligned.m8n8.x4.shared.b16 {%0,%1,%2,%3}, [%4];"
                 : "=r"(r[0]), "=r"(r[1]), "=r"(r[2]), "=r"(r[3]) : "r"(addr));
}
__device__ __forceinline__ void mma_h(float* c, const uint32_t* a, const uint32_t* b) {
    asm volatile("mma.sync.aligned.m16n8k16.row.col.f32.f16.f16.f32 "
                 "{%0,%1,%2,%3}, {%4,%5,%6,%7}, {%8,%9}, {%0,%1,%2,%3};"
                 : "+f"(c[0]), "+f"(c[1]), "+f"(c[2]), "+f"(c[3])
                 : "r"(a[0]), "r"(a[1]), "r"(a[2]), "r"(a[3]), "r"(b[0]), "r"(b[1]));
}
__device__ __forceinline__ float tanh_fast(float x) {
    float y;
    asm("tanh.approx.f32 %0, %1;" : "=f"(y) : "f"(x));
    return y;
}
__device__ __forceinline__ uint32_t swz(uint32_t off) {   // SW128: bits[6:4] ^= bits[9:7]
    return off ^ ((off >> 3) & 0x70);
}

// ============================================================================
// WIDE 1-pass fp16 GEMM: C[M,N] = A@B^T. CTA tile 128x128x64, 128 thr (2x2 warps,
// warp tile 64x64), acc 128 f32/thread, double-buffered cp.async, 2 CTAs/SM.
// mode 3: outF16[m*ldc+n] = D (fp16)            (W2^T)
// mode 1: D += bias; emit fp16 hi/lo only       (g_star)
// ============================================================================
#define KTILE      64
#define W_TILE_B   16384                 // 128 rows x 128 B
#define W_STG_B    (2 * W_TILE_B)        // A + B = 32 KB
#define W_SM_A(s)  ((s) * W_STG_B)
#define W_SM_B(s)  ((s) * W_STG_B + W_TILE_B)
#define WIDE_SMEM  (2 * W_STG_B)         // 64 KB

__device__ __forceinline__ void issue_stage_w(
    uint32_t sb, int s, int kt, const char* A, const char* B,
    int K, int bm, int bn, int tid)
{
    const int k0 = kt * KTILE;
#pragma unroll
    for (int i = 0; i < 8; i++) {
        int idx = tid + i * 128;
        int r = idx >> 3, c = idx & 7;
        uint32_t so = swz((uint32_t)(r * 128 + c * 16));
        size_t goA = ((size_t)(bm + r) * K + k0 + c * 8) * 2;
        size_t goB = ((size_t)(bn + r) * K + k0 + c * 8) * 2;
        asm volatile("cp.async.cg.shared.global [%0], [%1], 16;" :: "r"(sb + W_SM_A(s) + so), "l"(A + goA) : "memory");
        asm volatile("cp.async.cg.shared.global [%0], [%1], 16;" :: "r"(sb + W_SM_B(s) + so), "l"(B + goB) : "memory");
    }
    asm volatile("cp.async.commit_group;" ::: "memory");
}

__global__ void __launch_bounds__(128, 2) gemm_wide(
    const void* A_, const void* B_,
    int K, int KT, int mode, int ldc,
    const float* __restrict__ bias,
    __half* __restrict__ outH, __half* __restrict__ outL,
    __half* __restrict__ outF16)
{
    extern __shared__ char smem[];
    const uint32_t sb = smem_u32(smem);
    const int tid = threadIdx.x;
    const int wid = tid >> 5, lane = tid & 31;
    const int wm = wid & 1, wn = wid >> 1;          // 2(m) x 2(n)
    const int bm = blockIdx.y * 128, bn = blockIdx.x * 128;
    const char* A = (const char*)A_;
    const char* B = (const char*)B_;

    float acc[4][8][4];
#pragma unroll
    for (int a = 0; a < 4; a++)
#pragma unroll
        for (int b = 0; b < 8; b++)
#pragma unroll
            for (int c = 0; c < 4; c++) acc[a][b][c] = 0.f;

    const uint32_t a_row  = (uint32_t)(wm * 64 + (lane & 15));                         // + mi*16
    const uint32_t a_kofs = (uint32_t)(((lane >> 4) & 1) * 16);                        // + kk*32
    const uint32_t b_row  = (uint32_t)(wn * 64 + (lane & 7) + ((lane >> 4) & 1) * 8);  // + nq*16
    const uint32_t b_kofs = (uint32_t)(((lane >> 3) & 1) * 16);                        // + kk*32

    issue_stage_w(sb, 0, 0, A, B, K, bm, bn, tid);

    for (int kt = 0; kt < KT; kt++) {
        const int s = kt & 1;
        if (kt + 1 < KT) {
            issue_stage_w(sb, s ^ 1, kt + 1, A, B, K, bm, bn, tid);
            asm volatile("cp.async.wait_group 1;" ::: "memory");
        } else {
            asm volatile("cp.async.wait_group 0;" ::: "memory");
        }
        __syncthreads();

        const uint32_t aS = sb + W_SM_A(s), bS = sb + W_SM_B(s);
#pragma unroll
        for (int kk = 0; kk < 4; kk++) {
            uint32_t fA[4][4], fB[4][4];
#pragma unroll
            for (int mi = 0; mi < 4; mi++) {
                uint32_t off = swz((a_row + mi * 16) * 128 + kk * 32 + a_kofs);
                ldsm4(fA[mi], aS + off);
            }
#pragma unroll
            for (int nq = 0; nq < 4; nq++) {
                uint32_t off = swz((b_row + nq * 16) * 128 + kk * 32 + b_kofs);
                ldsm4(fB[nq], bS + off);
            }
#pragma unroll
            for (int mi = 0; mi < 4; mi++)
#pragma unroll
                for (int nt = 0; nt < 8; nt++)
                    mma_h(acc[mi][nt], fA[mi], &fB[nt >> 1][(nt & 1) * 2]);
        }
        __syncthreads();
    }

    // ---------------- epilogue ----------------
    const int g = lane >> 2, tig = lane & 3;
#pragma unroll
    for (int mi = 0; mi < 4; mi++) {
#pragma unroll
        for (int h = 0; h < 2; h++) {
            const int m = bm + wm * 64 + mi * 16 + g + h * 8;
#pragma unroll
            for (int nt = 0; nt < 8; nt++) {
                const int n = bn + wn * 64 + nt * 8 + 2 * tig;
                float x0 = acc[mi][nt][h * 2 + 0];
                float x1 = acc[mi][nt][h * 2 + 1];
                if (mode == 3) {
                    *(__half2*)&outF16[(size_t)m * ldc + n] = __floats2half2_rn(x0, x1);
                } else {   // mode 1
                    x0 += bias[n];  x1 += bias[n + 1];
                    __half h0 = __float2half_rn(x0), h1 = __float2half_rn(x1);
                    *(__half2*)&outH[(size_t)m * ldc + n] = __halves2half2(h0, h1);
                    *(__half2*)&outL[(size_t)m * ldc + n] = __halves2half2(
                        __float2half_rn(x0 - __half2float(h0)),
                        __float2half_rn(x1 - __half2float(h1)));
                }
            }
        }
    }
}

// ============================================================================
// NARROW 1-pass fp16 GEMM (GEMM3): C = A@B^T, fused scores epilogue.
// CTA tile 128x64x64, 128 thr (2x2 warps, warp tile 64x32), 2 CTAs/SM.
// ============================================================================
#define N_A_TILE_B  16384
#define N_B_TILE_B  8192
#define N_STG_B     (N_A_TILE_B + N_B_TILE_B)     // A + B = 24 KB
#define N_SM_A(s)   ((s) * N_STG_B)
#define N_SM_B(s)   ((s) * N_STG_B + N_A_TILE_B)
#define SCORES_SMEM (2 * N_STG_B)                 // 48 KB

__device__ __forceinline__ void issue_stage_n(
    uint32_t sb, int s, int kt,
    const char* A, const char* B,
    int K, int bm, int bn, int tid)
{
    const int k0 = kt * KTILE;
#pragma unroll
    for (int i = 0; i < 8; i++) {
        int idx = tid + i * 128;
        int r = idx >> 3, c = idx & 7;
        uint32_t so = swz((uint32_t)(r * 128 + c * 16));
        size_t go = ((size_t)(bm + r) * K + k0 + c * 8) * 2;
        asm volatile("cp.async.cg.shared.global [%0], [%1], 16;" :: "r"(sb + N_SM_A(s) + so), "l"(A + go) : "memory");
    }
#pragma unroll
    for (int i = 0; i < 4; i++) {
        int idx = tid + i * 128;
        int r = idx >> 3, c = idx & 7;
        uint32_t so = swz((uint32_t)(r * 128 + c * 16));
        size_t go = ((size_t)(bn + r) * K + k0 + c * 8) * 2;
        asm volatile("cp.async.cg.shared.global [%0], [%1], 16;" :: "r"(sb + N_SM_B(s) + so), "l"(B + go) : "memory");
    }
    asm volatile("cp.async.commit_group;" ::: "memory");
}

__global__ void __launch_bounds__(128, 2) gemm_scores(
    const void* A_, const void* B_,
    int K, int KT,
    const float* __restrict__ dec, const float* __restrict__ cov,
    const float* __restrict__ v, float* __restrict__ scores)
{
    extern __shared__ char smem[];
    const uint32_t sb = smem_u32(smem);
    const int tid = threadIdx.x;
    const int wid = tid >> 5, lane = tid & 31;
    const int wm = wid & 1, wn = wid >> 1;
    const int bm = blockIdx.y * 128, bn = blockIdx.x * 64;
    const char* A = (const char*)A_;
    const char* B = (const char*)B_;

    float acc[4][4][4];
#pragma unroll
    for (int a = 0; a < 4; a++)
#pragma unroll
        for (int b = 0; b < 4; b++)
#pragma unroll
            for (int c = 0; c < 4; c++) acc[a][b][c] = 0.f;

    const uint32_t a_row  = (uint32_t)(wm * 64 + (lane & 15));
    const uint32_t a_kofs = (uint32_t)(((lane >> 4) & 1) * 16);
    const uint32_t b_row  = (uint32_t)(wn * 32 + (lane & 7) + ((lane >> 4) & 1) * 8);
    const uint32_t b_kofs = (uint32_t)(((lane >> 3) & 1) * 16);

    issue_stage_n(sb, 0, 0, A, B, K, bm, bn, tid);

    for (int kt = 0; kt < KT; kt++) {
        const int s = kt & 1;
        if (kt + 1 < KT) {
            issue_stage_n(sb, s ^ 1, kt + 1, A, B, K, bm, bn, tid);
            asm volatile("cp.async.wait_group 1;" ::: "memory");
        } else {
            asm volatile("cp.async.wait_group 0;" ::: "memory");
        }
        __syncthreads();

        const uint32_t aS = sb + N_SM_A(s), bS = sb + N_SM_B(s);
#pragma unroll
        for (int kk = 0; kk < 4; kk++) {
            uint32_t fA[4][4], fB[2][4];
#pragma unroll
            for (int mi = 0; mi < 4; mi++) {
                uint32_t off = swz((a_row + mi * 16) * 128 + kk * 32 + a_kofs);
                ldsm4(fA[mi], aS + off);
            }
#pragma unroll
            for (int nq = 0; nq < 2; nq++) {
                uint32_t off = swz((b_row + nq * 16) * 128 + kk * 32 + b_kofs);
                ldsm4(fB[nq], bS + off);
            }
#pragma unroll
            for (int mi = 0; mi < 4; mi++)
#pragma unroll
                for (int nt = 0; nt < 4; nt++)
                    mma_h(acc[mi][nt], fA[mi], &fB[nt >> 1][(nt & 1) * 2]);
        }
        __syncthreads();
    }

    const int g = lane >> 2, tig = lane & 3;
#pragma unroll
    for (int mi = 0; mi < 4; mi++) {
#pragma unroll
        for (int h = 0; h < 2; h++) {
            const int m = bm + wm * 64 + mi * 16 + g + h * 8;
            const float cv = cov[m];
            const int bofs = (m / TK) * DH;
            float rsum = 0.f;
#pragma unroll
            for (int nt = 0; nt < 4; nt++) {
                const int n = bn + wn * 32 + nt * 8 + 2 * tig;
                rsum += tanh_fast(acc[mi][nt][h * 2 + 0] + dec[bofs + n] + cv) * v[n];
                rsum += tanh_fast(acc[mi][nt][h * 2 + 1] + dec[bofs + n + 1] + cv) * v[n + 1];
            }
            rsum += __shfl_xor_sync(0xffffffffu, rsum, 1);
            rsum += __shfl_xor_sync(0xffffffffu, rsum, 2);
            if (tig == 0) atomicAdd(&scores[m], rsum);
        }
    }
}

// ============================ conversion kernels ============================
// fp32 -> fp16 single, 4 independent float4 loads per thread (MLP=4).
// n4 must be divisible by 1024 (block covers 1024 float4s).
__global__ void __launch_bounds__(256) csingle_h4(
    const float4* __restrict__ in, __half2* __restrict__ oh, int n4)
{
    const int base = blockIdx.x * 1024 + threadIdx.x;
    float4 x[4];
#pragma unroll
    for (int j = 0; j < 4; j++) x[j] = in[base + j * 256];
#pragma unroll
    for (int j = 0; j < 4; j++) {
        const int i = base + j * 256;
        oh[2 * i]     = __floats2half2_rn(x[j].x, x[j].y);
        oh[2 * i + 1] = __floats2half2_rn(x[j].z, x[j].w);
    }
}

__global__ void __launch_bounds__(256) tconv_h1(
    const float* __restrict__ in, __half* __restrict__ oh, int R, int C)
{
    __shared__ float t[32][33];
    const int bx = blockIdx.x * 32, by = blockIdx.y * 32;
    const int x = threadIdx.x & 31, y = threadIdx.x >> 5;
#pragma unroll
    for (int i = 0; i < 32; i += 8)
        t[y + i][x] = in[(size_t)(by + y + i) * C + bx + x];
    __syncthreads();
#pragma unroll
    for (int i = 0; i < 32; i += 8) {
        float val = t[x][y + i];
        oh[(size_t)(bx + y + i) * R + by + x] = __float2half_rn(val);
    }
}

// ============================ small kernels ============================
__global__ void __launch_bounds__(256) b2_kernel(
    const float* __restrict__ bg, const float* __restrict__ Gs,
    const float* __restrict__ bgs, float* __restrict__ b2)
{
    const int j  = blockIdx.x * 256 + threadIdx.x;
    const int k0 = blockIdx.y * 512;
    float s = 0.f;
#pragma unroll 8
    for (int i = 0; i < 512; i++)
        s += bg[k0 + i] * Gs[(size_t)(k0 + i) * DH + j];
    if (blockIdx.y == 0) s += bgs[j];
    atomicAdd(&b2[j], s);
}

__global__ void __launch_bounds__(256) dec_kernel(
    const float* __restrict__ s_t_hat, const float* __restrict__ Wdec,
    const float* __restrict__ bdec, float* __restrict__ dec)
{
    const int idx = blockIdx.x * 256 + threadIdx.x;
    const int b = idx >> 10, j = idx & (DH - 1);
    float s = bdec[j];
#pragma unroll 8
    for (int k = 0; k < DH; k++) s += s_t_hat[b * DH + k] * Wdec[(size_t)k * DH + j];
    dec[idx] = s;
}

__global__ void __launch_bounds__(256) softmax_kernel(
    const float* __restrict__ scores, const float* __restrict__ cov,
    float* __restrict__ alpha, float* __restrict__ out)
{
    const int b = blockIdx.x, t = threadIdx.x;
    __shared__ float red[8];
    __shared__ float smax, ssum;
    float sv = (t < TK) ? scores[b * TK + t] : -3.4e38f;

    float m = sv;
#pragma unroll
    for (int o = 16; o > 0; o >>= 1) m = fmaxf(m, __shfl_xor_sync(0xffffffffu, m, o));
    if ((t & 31) == 0) red[t >> 5] = m;
    __syncthreads();
    if (t < 8) {
        m = red[t];
#pragma unroll
        for (int o = 4; o > 0; o >>= 1) m = fmaxf(m, __shfl_xor_sync(0xffu, m, o));
        if (t == 0) smax = m;
    }
    __syncthreads();

    float e = (t < TK) ? expf(sv - smax) : 0.f;
    float su = e;
#pragma unroll
    for (int o = 16; o > 0; o >>= 1) su += __shfl_xor_sync(0xffffffffu, su, o);
    if ((t & 31) == 0) red[t >> 5] = su;
    __syncthreads();
    if (t < 8) {
        su = red[t];
#pragma unroll
        for (int o = 4; o > 0; o >>= 1) su += __shfl_xor_sync(0xffu, su, o);
        if (t == 0) ssum = su;
    }
    __syncthreads();

    if (t < TK) {
        const float a = e / ssum;
        alpha[b * TK + t] = a;
        out[OUT_ALPHA + b * TK + t] = a;
        out[OUT_COV + b * TK + t] = cov[b * TK + t] + a;
    }
}

// c_img from fp16 hi/lo reconstruction of g_star; half2-vectorized, 128-thr blocks
__global__ void __launch_bounds__(128) cimg_kernel(
    const __half2* __restrict__ gsH, const __half2* __restrict__ gsL,
    const float* __restrict__ alpha, float* __restrict__ out)
{
    const int b = blockIdx.y;
    const int d2 = blockIdx.x * 128 + threadIdx.x;   // half2 index: 0..DH/2-1
    __shared__ float sal[TK];
    for (int t = threadIdx.x; t < TK; t += 128) sal[t] = alpha[b * TK + t];
    __syncthreads();
    float s0 = 0.f, s1 = 0.f;
#pragma unroll 4
    for (int t = 0; t < TK; t++) {
        size_t idx = ((size_t)(b * TK + t)) * (DH / 2) + d2;
        float2 h = __half22float2(gsH[idx]);
        float2 l = __half22float2(gsL[idx]);
        s0 += sal[t] * (h.x + l.x);
        s1 += sal[t] * (h.y + l.y);
    }
    *(float2*)&out[OUT_C + b * DH + 2 * d2] = make_float2(s0, s1);
}

// ============================ launch ============================
extern "C" void kernel_launch(void* const* d_in, const int* in_sizes, int n_in,
                              void* d_out, int out_size)
{
    const float* gf   = (const float*)d_in[0];
    const float* sth  = (const float*)d_in[1];
    const float* cov  = (const float*)d_in[2];
    const float* Wg   = (const float*)d_in[3];
    const float* bg   = (const float*)d_in[4];
    const float* Gs   = (const float*)d_in[5];
    const float* bgs  = (const float*)d_in[6];
    const float* Wgs  = (const float*)d_in[7];
    const float* Wdec = (const float*)d_in[8];
    const float* bdec = (const float*)d_in[9];
    const float* v    = (const float*)d_in[10];
    float* out = (float*)d_out;

    __half *WgF, *GsTF, *W2TF, *gfF, *WgsTF, *gsH, *gsL;
    float *b2p, *decp, *scoresp, *alphap;
    cudaGetSymbolAddress((void**)&WgF, g_WgF);
    cudaGetSymbolAddress((void**)&GsTF, g_GsTF);
    cudaGetSymbolAddress((void**)&W2TF, g_W2TF);
    cudaGetSymbolAddress((void**)&gfF, g_gfF);
    cudaGetSymbolAddress((void**)&WgsTF, g_WgsTF);
    cudaGetSymbolAddress((void**)&gsH, g_gsH);     cudaGetSymbolAddress((void**)&gsL, g_gsL);
    cudaGetSymbolAddress((void**)&b2p, g_b2);      cudaGetSymbolAddress((void**)&decp, g_dec);
    cudaGetSymbolAddress((void**)&scoresp, g_scores);
    cudaGetSymbolAddress((void**)&alphap, g_alpha);

    cudaFuncSetAttribute(gemm_wide,   cudaFuncAttributeMaxDynamicSharedMemorySize, WIDE_SMEM);
    cudaFuncSetAttribute(gemm_scores, cudaFuncAttributeMaxDynamicSharedMemorySize, SCORES_SMEM);

    // Side stream + events (created once; resources, not work)
    static cudaStream_t sideS = nullptr;
    static cudaEvent_t evFork0 = nullptr, evFork1 = nullptr, evGs = nullptr, evJoin = nullptr;
    if (sideS == nullptr) {
        cudaStreamCreateWithFlags(&sideS, cudaStreamNonBlocking);
        cudaEventCreateWithFlags(&evFork0, cudaEventDisableTiming);
        cudaEventCreateWithFlags(&evFork1, cudaEventDisableTiming);
        cudaEventCreateWithFlags(&evGs, cudaEventDisableTiming);
        cudaEventCreateWithFlags(&evJoin, cudaEventDisableTiming);
    }

    // ---- fork 0 at stream start: side work (runs under main's Wg conversion) ----
    cudaEventRecord(evFork0, 0);
    cudaStreamWaitEvent(sideS, evFork0, 0);
    // Gs tconv first (GEMM1's A operand) so it finishes inside the Wg-conv window
    {   dim3 g(DH / 32, GFD / 32);  tconv_h1<<<g, 256, 0, sideS>>>(Gs, GsTF, GFD, DH); }
    cudaEventRecord(evGs, sideS);
    cudaMemsetAsync(b2p, 0, DH * sizeof(float), sideS);
    cudaMemsetAsync(scoresp, 0, BT * sizeof(float), sideS);
    {   dim3 g(DH / 256, 8);  b2_kernel<<<g, 256, 0, sideS>>>(bg, Gs, bgs, b2p); }
    {   dim3 g(DH / 32, DH / 32);  tconv_h1<<<g, 256, 0, sideS>>>(Wgs, WgsTF, DH, DH); }
    dec_kernel<<<(BATCH * DH) / 256, 256, 0, sideS>>>(sth, Wdec, bdec, decp);

    // ---- main: Wg conversion (heavy DRAM) ----
    csingle_h4<<<(GFD * GFD / 4) / 1024, 256>>>((const float4*)Wg, (__half2*)WgF, GFD * GFD / 4);
    // wait for Gs^T before GEMM1
    cudaStreamWaitEvent(0, evGs, 0);
    // fork 1: gf conversion overlaps with compute-bound GEMM1
    cudaEventRecord(evFork1, 0);
    // GEMM1 (wide 1-pass): W2T[DH,GFD] = GsT @ Wg^T -> fp16, ldc=GFD
    {
        dim3 grid(GFD / 128, DH / 128);
        gemm_wide<<<grid, 128, WIDE_SMEM>>>(GsTF, WgF, GFD, GFD / KTILE, 3, GFD,
            nullptr, nullptr, nullptr, W2TF);
    }

    // ---- side: gf conversion hidden under GEMM1 ----
    cudaStreamWaitEvent(sideS, evFork1, 0);
    csingle_h4<<<(BT * GFD / 4) / 1024, 256, 0, sideS>>>((const float4*)gf,
        (__half2*)gfF, BT * GFD / 4);
    cudaEventRecord(evJoin, sideS);

    // ---- main: join, then dependent GEMMs ----
    cudaStreamWaitEvent(0, evJoin, 0);
    // GEMM2 (wide 1-pass): g_star = gf @ W2 + b2 -> fp16 hi/lo, ldc=DH
    {
        dim3 grid(DH / 128, BT / 128);
        gemm_wide<<<grid, 128, WIDE_SMEM>>>(gfF, W2TF, GFD, GFD / KTILE, 1, DH,
            b2p, gsH, gsL, nullptr);
    }
    // GEMM3 (narrow 1-pass, fused): scores = tanh(gsH@Wgs + dec + cov) . v
    {
        dim3 grid(DH / 64, BT / 128);
        gemm_scores<<<grid, 128, SCORES_SMEM>>>(gsH, WgsTF, DH, DH / KTILE,
            decp, cov, v, scoresp);
    }
    // softmax + outputs
    softmax_kernel<<<BATCH, 256>>>(scoresp, cov, alphap, out);
    // context vector (reads fp16 hi/lo, half2-vectorized)
    {   dim3 grid(DH / 256, BATCH);  cimg_kernel<<<grid, 128>>>((const __half2*)gsH, (const __half2*)gsL, alphap, out); }
}

// round 16
// speedup vs baseline: 1.4987x; 1.4987x over previous
#include <cuda_runtime.h>
#include <cuda_bf16.h>
#include <cuda_fp16.h>
#include <cstdint>
#include <math.h>

#define GFD   4096
#define DH    1024
#define BATCH 32
#define TK    196
#define BT    (BATCH * TK)   // 6272

// Output layout in d_out (float): c_img[32,1024] | coverage_new[32,196,1] | alpha[32,196,1]
#define OUT_C      0
#define OUT_COV    (BATCH * DH)
#define OUT_ALPHA  (BATCH * DH + BT)

// ============================ scratch (__device__ globals) ============================
__device__ __align__(1024) __half g_WgF[GFD * GFD];    // Wg fp16 [GFD, GFD] row-major (K contiguous)
__device__ __align__(1024) __half g_GsTF[DH * GFD];    // Gs^T fp16 single [DH, GFD]
__device__ __align__(1024) __half g_W2TF[DH * GFD];    // W2^T fp16 single [DH, GFD]
__device__ __align__(1024) __half g_gfF[BT * GFD];     // gf fp16 single
__device__ __align__(1024) __half g_WgsTF[DH * DH];    // Wgs^T fp16 single [DH, DH]
__device__ __align__(1024) __half g_gsH[BT * DH];      // g_star fp16 hi
__device__ __align__(1024) __half g_gsL[BT * DH];      // g_star fp16 lo (cimg only)
__device__ float g_b2[DH];
__device__ float g_dec[BATCH * DH];
__device__ float g_scores[BT];
__device__ float g_alpha[BT];

// ============================ helpers ============================
__device__ __forceinline__ uint32_t smem_u32(const void* p) {
    uint32_t a;
    asm("{ .reg .u64 t; cvta.to.shared.u64 t, %1; cvt.u32.u64 %0, t; }" : "=r"(a) : "l"(p));
    return a;
}
__device__ __forceinline__ void ldsm4(uint32_t* r, uint32_t addr) {
    asm volatile("ldmatrix.sync.aligned.m8n8.x4.shared.b16 {%0,%1,%2,%3}, [%4];"
                 : "=r"(r[0]), "=r"(r[1]), "=r"(r[2]), "=r"(r[3]) : "r"(addr));
}
__device__ __forceinline__ void mma_h(float* c, const uint32_t* a, const uint32_t* b) {
    asm volatile("mma.sync.aligned.m16n8k16.row.col.f32.f16.f16.f32 "
                 "{%0,%1,%2,%3}, {%4,%5,%6,%7}, {%8,%9}, {%0,%1,%2,%3};"
                 : "+f"(c[0]), "+f"(c[1]), "+f"(c[2]), "+f"(c[3])
                 : "r"(a[0]), "r"(a[1]), "r"(a[2]), "r"(a[3]), "r"(b[0]), "r"(b[1]));
}
__device__ __forceinline__ float tanh_fast(float x) {
    float y;
    asm("tanh.approx.f32 %0, %1;" : "=f"(y) : "f"(x));
    return y;
}
__device__ __forceinline__ uint32_t swz(uint32_t off) {   // SW128: bits[6:4] ^= bits[9:7]
    return off ^ ((off >> 3) & 0x70);
}

// ============================================================================
// WIDE 1-pass fp16 GEMM: C[M,N] = A@B^T. CTA tile 128x128x64, 128 thr (2x2 warps,
// warp tile 64x64), acc 128 f32/thread, double-buffered cp.async, 2 CTAs/SM.
// mode 3: outF16[m*ldc+n] = D (fp16)            (W2^T)
// mode 1: D += bias; emit fp16 hi/lo only       (g_star)
// ============================================================================
#define KTILE      64
#define W_TILE_B   16384                 // 128 rows x 128 B
#define W_STG_B    (2 * W_TILE_B)        // A + B = 32 KB
#define W_SM_A(s)  ((s) * W_STG_B)
#define W_SM_B(s)  ((s) * W_STG_B + W_TILE_B)
#define WIDE_SMEM  (2 * W_STG_B)         // 64 KB

__device__ __forceinline__ void issue_stage_w(
    uint32_t sb, int s, int kt, const char* A, const char* B,
    int K, int bm, int bn, int tid)
{
    const int k0 = kt * KTILE;
#pragma unroll
    for (int i = 0; i < 8; i++) {
        int idx = tid + i * 128;
        int r = idx >> 3, c = idx & 7;
        uint32_t so = swz((uint32_t)(r * 128 + c * 16));
        size_t goA = ((size_t)(bm + r) * K + k0 + c * 8) * 2;
        size_t goB = ((size_t)(bn + r) * K + k0 + c * 8) * 2;
        asm volatile("cp.async.cg.shared.global [%0], [%1], 16;" :: "r"(sb + W_SM_A(s) + so), "l"(A + goA) : "memory");
        asm volatile("cp.async.cg.shared.global [%0], [%1], 16;" :: "r"(sb + W_SM_B(s) + so), "l"(B + goB) : "memory");
    }
    asm volatile("cp.async.commit_group;" ::: "memory");
}

__global__ void __launch_bounds__(128, 2) gemm_wide(
    const void* A_, const void* B_,
    int K, int KT, int mode, int ldc,
    const float* __restrict__ bias,
    __half* __restrict__ outH, __half* __restrict__ outL,
    __half* __restrict__ outF16)
{
    extern __shared__ char smem[];
    const uint32_t sb = smem_u32(smem);
    const int tid = threadIdx.x;
    const int wid = tid >> 5, lane = tid & 31;
    const int wm = wid & 1, wn = wid >> 1;          // 2(m) x 2(n)
    const int bm = blockIdx.y * 128, bn = blockIdx.x * 128;
    const char* A = (const char*)A_;
    const char* B = (const char*)B_;

    float acc[4][8][4];
#pragma unroll
    for (int a = 0; a < 4; a++)
#pragma unroll
        for (int b = 0; b < 8; b++)
#pragma unroll
            for (int c = 0; c < 4; c++) acc[a][b][c] = 0.f;

    const uint32_t a_row  = (uint32_t)(wm * 64 + (lane & 15));                         // + mi*16
    const uint32_t a_kofs = (uint32_t)(((lane >> 4) & 1) * 16);                        // + kk*32
    const uint32_t b_row  = (uint32_t)(wn * 64 + (lane & 7) + ((lane >> 4) & 1) * 8);  // + nq*16
    const uint32_t b_kofs = (uint32_t)(((lane >> 3) & 1) * 16);                        // + kk*32

    issue_stage_w(sb, 0, 0, A, B, K, bm, bn, tid);

    for (int kt = 0; kt < KT; kt++) {
        const int s = kt & 1;
        if (kt + 1 < KT) {
            issue_stage_w(sb, s ^ 1, kt + 1, A, B, K, bm, bn, tid);
            asm volatile("cp.async.wait_group 1;" ::: "memory");
        } else {
            asm volatile("cp.async.wait_group 0;" ::: "memory");
        }
        __syncthreads();

        const uint32_t aS = sb + W_SM_A(s), bS = sb + W_SM_B(s);
#pragma unroll
        for (int kk = 0; kk < 4; kk++) {
            uint32_t fA[4][4], fB[4][4];
#pragma unroll
            for (int mi = 0; mi < 4; mi++) {
                uint32_t off = swz((a_row + mi * 16) * 128 + kk * 32 + a_kofs);
                ldsm4(fA[mi], aS + off);
            }
#pragma unroll
            for (int nq = 0; nq < 4; nq++) {
                uint32_t off = swz((b_row + nq * 16) * 128 + kk * 32 + b_kofs);
                ldsm4(fB[nq], bS + off);
            }
#pragma unroll
            for (int mi = 0; mi < 4; mi++)
#pragma unroll
                for (int nt = 0; nt < 8; nt++)
                    mma_h(acc[mi][nt], fA[mi], &fB[nt >> 1][(nt & 1) * 2]);
        }
        __syncthreads();
    }

    // ---------------- epilogue ----------------
    const int g = lane >> 2, tig = lane & 3;
#pragma unroll
    for (int mi = 0; mi < 4; mi++) {
#pragma unroll
        for (int h = 0; h < 2; h++) {
            const int m = bm + wm * 64 + mi * 16 + g + h * 8;
#pragma unroll
            for (int nt = 0; nt < 8; nt++) {
                const int n = bn + wn * 64 + nt * 8 + 2 * tig;
                float x0 = acc[mi][nt][h * 2 + 0];
                float x1 = acc[mi][nt][h * 2 + 1];
                if (mode == 3) {
                    *(__half2*)&outF16[(size_t)m * ldc + n] = __floats2half2_rn(x0, x1);
                } else {   // mode 1
                    x0 += bias[n];  x1 += bias[n + 1];
                    __half h0 = __float2half_rn(x0), h1 = __float2half_rn(x1);
                    *(__half2*)&outH[(size_t)m * ldc + n] = __halves2half2(h0, h1);
                    *(__half2*)&outL[(size_t)m * ldc + n] = __halves2half2(
                        __float2half_rn(x0 - __half2float(h0)),
                        __float2half_rn(x1 - __half2float(h1)));
                }
            }
        }
    }
}

// ============================================================================
// NARROW 1-pass fp16 GEMM (GEMM3): C = A@B^T, fused scores epilogue.
// CTA tile 128x64x64, 128 thr (2x2 warps, warp tile 64x32), 2 CTAs/SM.
// ============================================================================
#define N_A_TILE_B  16384
#define N_B_TILE_B  8192
#define N_STG_B     (N_A_TILE_B + N_B_TILE_B)     // A + B = 24 KB
#define N_SM_A(s)   ((s) * N_STG_B)
#define N_SM_B(s)   ((s) * N_STG_B + N_A_TILE_B)
#define SCORES_SMEM (2 * N_STG_B)                 // 48 KB

__device__ __forceinline__ void issue_stage_n(
    uint32_t sb, int s, int kt,
    const char* A, const char* B,
    int K, int bm, int bn, int tid)
{
    const int k0 = kt * KTILE;
#pragma unroll
    for (int i = 0; i < 8; i++) {
        int idx = tid + i * 128;
        int r = idx >> 3, c = idx & 7;
        uint32_t so = swz((uint32_t)(r * 128 + c * 16));
        size_t go = ((size_t)(bm + r) * K + k0 + c * 8) * 2;
        asm volatile("cp.async.cg.shared.global [%0], [%1], 16;" :: "r"(sb + N_SM_A(s) + so), "l"(A + go) : "memory");
    }
#pragma unroll
    for (int i = 0; i < 4; i++) {
        int idx = tid + i * 128;
        int r = idx >> 3, c = idx & 7;
        uint32_t so = swz((uint32_t)(r * 128 + c * 16));
        size_t go = ((size_t)(bn + r) * K + k0 + c * 8) * 2;
        asm volatile("cp.async.cg.shared.global [%0], [%1], 16;" :: "r"(sb + N_SM_B(s) + so), "l"(B + go) : "memory");
    }
    asm volatile("cp.async.commit_group;" ::: "memory");
}

__global__ void __launch_bounds__(128, 2) gemm_scores(
    const void* A_, const void* B_,
    int K, int KT,
    const float* __restrict__ dec, const float* __restrict__ cov,
    const float* __restrict__ v, float* __restrict__ scores)
{
    extern __shared__ char smem[];
    const uint32_t sb = smem_u32(smem);
    const int tid = threadIdx.x;
    const int wid = tid >> 5, lane = tid & 31;
    const int wm = wid & 1, wn = wid >> 1;
    const int bm = blockIdx.y * 128, bn = blockIdx.x * 64;
    const char* A = (const char*)A_;
    const char* B = (const char*)B_;

    float acc[4][4][4];
#pragma unroll
    for (int a = 0; a < 4; a++)
#pragma unroll
        for (int b = 0; b < 4; b++)
#pragma unroll
            for (int c = 0; c < 4; c++) acc[a][b][c] = 0.f;

    const uint32_t a_row  = (uint32_t)(wm * 64 + (lane & 15));
    const uint32_t a_kofs = (uint32_t)(((lane >> 4) & 1) * 16);
    const uint32_t b_row  = (uint32_t)(wn * 32 + (lane & 7) + ((lane >> 4) & 1) * 8);
    const uint32_t b_kofs = (uint32_t)(((lane >> 3) & 1) * 16);

    issue_stage_n(sb, 0, 0, A, B, K, bm, bn, tid);

    for (int kt = 0; kt < KT; kt++) {
        const int s = kt & 1;
        if (kt + 1 < KT) {
            issue_stage_n(sb, s ^ 1, kt + 1, A, B, K, bm, bn, tid);
            asm volatile("cp.async.wait_group 1;" ::: "memory");
        } else {
            asm volatile("cp.async.wait_group 0;" ::: "memory");
        }
        __syncthreads();

        const uint32_t aS = sb + N_SM_A(s), bS = sb + N_SM_B(s);
#pragma unroll
        for (int kk = 0; kk < 4; kk++) {
            uint32_t fA[4][4], fB[2][4];
#pragma unroll
            for (int mi = 0; mi < 4; mi++) {
                uint32_t off = swz((a_row + mi * 16) * 128 + kk * 32 + a_kofs);
                ldsm4(fA[mi], aS + off);
            }
#pragma unroll
            for (int nq = 0; nq < 2; nq++) {
                uint32_t off = swz((b_row + nq * 16) * 128 + kk * 32 + b_kofs);
                ldsm4(fB[nq], bS + off);
            }
#pragma unroll
            for (int mi = 0; mi < 4; mi++)
#pragma unroll
                for (int nt = 0; nt < 4; nt++)
                    mma_h(acc[mi][nt], fA[mi], &fB[nt >> 1][(nt & 1) * 2]);
        }
        __syncthreads();
    }

    const int g = lane >> 2, tig = lane & 3;
#pragma unroll
    for (int mi = 0; mi < 4; mi++) {
#pragma unroll
        for (int h = 0; h < 2; h++) {
            const int m = bm + wm * 64 + mi * 16 + g + h * 8;
            const float cv = cov[m];
            const int bofs = (m / TK) * DH;
            float rsum = 0.f;
#pragma unroll
            for (int nt = 0; nt < 4; nt++) {
                const int n = bn + wn * 32 + nt * 8 + 2 * tig;
                rsum += tanh_fast(acc[mi][nt][h * 2 + 0] + dec[bofs + n] + cv) * v[n];
                rsum += tanh_fast(acc[mi][nt][h * 2 + 1] + dec[bofs + n + 1] + cv) * v[n + 1];
            }
            rsum += __shfl_xor_sync(0xffffffffu, rsum, 1);
            rsum += __shfl_xor_sync(0xffffffffu, rsum, 2);
            if (tig == 0) atomicAdd(&scores[m], rsum);
        }
    }
}

// ============================ conversion kernels ============================
// fp32 -> fp16 single, 4 independent float4 loads per thread (MLP=4).
__global__ void __launch_bounds__(256) csingle_h4(
    const float4* __restrict__ in, __half2* __restrict__ oh, int n4)
{
    const int base = blockIdx.x * 1024 + threadIdx.x;
    float4 x[4];
#pragma unroll
    for (int j = 0; j < 4; j++) x[j] = in[base + j * 256];
#pragma unroll
    for (int j = 0; j < 4; j++) {
        const int i = base + j * 256;
        oh[2 * i]     = __floats2half2_rn(x[j].x, x[j].y);
        oh[2 * i + 1] = __floats2half2_rn(x[j].z, x[j].w);
    }
}

__global__ void __launch_bounds__(256) tconv_h1(
    const float* __restrict__ in, __half* __restrict__ oh, int R, int C)
{
    __shared__ float t[32][33];
    const int bx = blockIdx.x * 32, by = blockIdx.y * 32;
    const int x = threadIdx.x & 31, y = threadIdx.x >> 5;
#pragma unroll
    for (int i = 0; i < 32; i += 8)
        t[y + i][x] = in[(size_t)(by + y + i) * C + bx + x];
    __syncthreads();
#pragma unroll
    for (int i = 0; i < 32; i += 8) {
        float val = t[x][y + i];
        oh[(size_t)(bx + y + i) * R + by + x] = __float2half_rn(val);
    }
}

// ============================ small kernels ============================
__global__ void __launch_bounds__(256) b2_kernel(
    const float* __restrict__ bg, const float* __restrict__ Gs,
    const float* __restrict__ bgs, float* __restrict__ b2)
{
    const int j  = blockIdx.x * 256 + threadIdx.x;
    const int k0 = blockIdx.y * 512;
    float s = 0.f;
#pragma unroll 8
    for (int i = 0; i < 512; i++)
        s += bg[k0 + i] * Gs[(size_t)(k0 + i) * DH + j];
    if (blockIdx.y == 0) s += bgs[j];
    atomicAdd(&b2[j], s);
}

// dec += partial(s_t_hat @ Wdec) over K-chunk of 256; chunk 0 adds bdec.
// dec must be pre-zeroed. grid (BATCH*DH/256, 4).
__global__ void __launch_bounds__(256) dec_kernel(
    const float* __restrict__ s_t_hat, const float* __restrict__ Wdec,
    const float* __restrict__ bdec, float* __restrict__ dec)
{
    const int idx = blockIdx.x * 256 + threadIdx.x;
    const int b = idx >> 10, j = idx & (DH - 1);
    const int k0 = blockIdx.y * 256;
    float s = 0.f;
#pragma unroll 8
    for (int k = 0; k < 256; k++)
        s += s_t_hat[b * DH + k0 + k] * Wdec[(size_t)(k0 + k) * DH + j];
    if (blockIdx.y == 0) s += bdec[j];
    atomicAdd(&dec[idx], s);
}

__global__ void __launch_bounds__(256) softmax_kernel(
    const float* __restrict__ scores, const float* __restrict__ cov,
    float* __restrict__ alpha, float* __restrict__ out)
{
    const int b = blockIdx.x, t = threadIdx.x;
    __shared__ float red[8];
    __shared__ float smax, ssum;
    float sv = (t < TK) ? scores[b * TK + t] : -3.4e38f;

    float m = sv;
#pragma unroll
    for (int o = 16; o > 0; o >>= 1) m = fmaxf(m, __shfl_xor_sync(0xffffffffu, m, o));
    if ((t & 31) == 0) red[t >> 5] = m;
    __syncthreads();
    if (t < 8) {
        m = red[t];
#pragma unroll
        for (int o = 4; o > 0; o >>= 1) m = fmaxf(m, __shfl_xor_sync(0xffu, m, o));
        if (t == 0) smax = m;
    }
    __syncthreads();

    float e = (t < TK) ? expf(sv - smax) : 0.f;
    float su = e;
#pragma unroll
    for (int o = 16; o > 0; o >>= 1) su += __shfl_xor_sync(0xffffffffu, su, o);
    if ((t & 31) == 0) red[t >> 5] = su;
    __syncthreads();
    if (t < 8) {
        su = red[t];
#pragma unroll
        for (int o = 4; o > 0; o >>= 1) su += __shfl_xor_sync(0xffu, su, o);
        if (t == 0) ssum = su;
    }
    __syncthreads();

    if (t < TK) {
        const float a = e / ssum;
        alpha[b * TK + t] = a;
        out[OUT_ALPHA + b * TK + t] = a;
        out[OUT_COV + b * TK + t] = cov[b * TK + t] + a;
    }
}

// c_img from fp16 hi/lo reconstruction of g_star; half2-vectorized, 128-thr blocks
__global__ void __launch_bounds__(128) cimg_kernel(
    const __half2* __restrict__ gsH, const __half2* __restrict__ gsL,
    const float* __restrict__ alpha, float* __restrict__ out)
{
    const int b = blockIdx.y;
    const int d2 = blockIdx.x * 128 + threadIdx.x;   // half2 index: 0..DH/2-1
    __shared__ float sal[TK];
    for (int t = threadIdx.x; t < TK; t += 128) sal[t] = alpha[b * TK + t];
    __syncthreads();
    float s0 = 0.f, s1 = 0.f;
#pragma unroll 4
    for (int t = 0; t < TK; t++) {
        size_t idx = ((size_t)(b * TK + t)) * (DH / 2) + d2;
        float2 h = __half22float2(gsH[idx]);
        float2 l = __half22float2(gsL[idx]);
        s0 += sal[t] * (h.x + l.x);
        s1 += sal[t] * (h.y + l.y);
    }
    *(float2*)&out[OUT_C + b * DH + 2 * d2] = make_float2(s0, s1);
}

// ============================ launch ============================
extern "C" void kernel_launch(void* const* d_in, const int* in_sizes, int n_in,
                              void* d_out, int out_size)
{
    const float* gf   = (const float*)d_in[0];
    const float* sth  = (const float*)d_in[1];
    const float* cov  = (const float*)d_in[2];
    const float* Wg   = (const float*)d_in[3];
    const float* bg   = (const float*)d_in[4];
    const float* Gs   = (const float*)d_in[5];
    const float* bgs  = (const float*)d_in[6];
    const float* Wgs  = (const float*)d_in[7];
    const float* Wdec = (const float*)d_in[8];
    const float* bdec = (const float*)d_in[9];
    const float* v    = (const float*)d_in[10];
    float* out = (float*)d_out;

    __half *WgF, *GsTF, *W2TF, *gfF, *WgsTF, *gsH, *gsL;
    float *b2p, *decp, *scoresp, *alphap;
    cudaGetSymbolAddress((void**)&WgF, g_WgF);
    cudaGetSymbolAddress((void**)&GsTF, g_GsTF);
    cudaGetSymbolAddress((void**)&W2TF, g_W2TF);
    cudaGetSymbolAddress((void**)&gfF, g_gfF);
    cudaGetSymbolAddress((void**)&WgsTF, g_WgsTF);
    cudaGetSymbolAddress((void**)&gsH, g_gsH);     cudaGetSymbolAddress((void**)&gsL, g_gsL);
    cudaGetSymbolAddress((void**)&b2p, g_b2);      cudaGetSymbolAddress((void**)&decp, g_dec);
    cudaGetSymbolAddress((void**)&scoresp, g_scores);
    cudaGetSymbolAddress((void**)&alphap, g_alpha);

    cudaFuncSetAttribute(gemm_wide,   cudaFuncAttributeMaxDynamicSharedMemorySize, WIDE_SMEM);
    cudaFuncSetAttribute(gemm_scores, cudaFuncAttributeMaxDynamicSharedMemorySize, SCORES_SMEM);

    // Side stream + events (created once; resources, not work)
    static cudaStream_t sideS = nullptr;
    static cudaEvent_t evFork0 = nullptr, evFork1 = nullptr, evJoin = nullptr;
    if (sideS == nullptr) {
        cudaStreamCreateWithFlags(&sideS, cudaStreamNonBlocking);
        cudaEventCreateWithFlags(&evFork0, cudaEventDisableTiming);
        cudaEventCreateWithFlags(&evFork1, cudaEventDisableTiming);
        cudaEventCreateWithFlags(&evJoin, cudaEventDisableTiming);
    }

    // ---- fork 0 at stream start: small side work (low DRAM footprint) ----
    // dec (the former long pole, now K-split x4) goes FIRST.
    cudaEventRecord(evFork0, 0);
    cudaStreamWaitEvent(sideS, evFork0, 0);
    cudaMemsetAsync(decp, 0, BATCH * DH * sizeof(float), sideS);
    cudaMemsetAsync(b2p, 0, DH * sizeof(float), sideS);
    cudaMemsetAsync(scoresp, 0, BT * sizeof(float), sideS);
    {   dim3 g((BATCH * DH) / 256, 4);  dec_kernel<<<g, 256, 0, sideS>>>(sth, Wdec, bdec, decp); }
    {   dim3 g(DH / 256, 8);  b2_kernel<<<g, 256, 0, sideS>>>(bg, Gs, bgs, b2p); }
    {   dim3 g(DH / 32, DH / 32);  tconv_h1<<<g, 256, 0, sideS>>>(Wgs, WgsTF, DH, DH); }

    // ---- main: DRAM-bound conversions (exclusive heavy DRAM use) ----
    // Wg -> fp16 single (MLP-4)
    csingle_h4<<<(GFD * GFD / 4) / 1024, 256>>>((const float4*)Wg, (__half2*)WgF, GFD * GFD / 4);
    // Gs -> Gs^T fp16 single
    {   dim3 g(DH / 32, GFD / 32);  tconv_h1<<<g, 256>>>(Gs, GsTF, GFD, DH); }
    // fork 1 AFTER main's conversions: gf conversion overlaps only with compute-bound GEMM1
    cudaEventRecord(evFork1, 0);
    // GEMM1 (wide 1-pass): W2T[DH,GFD] = GsT @ Wg^T -> fp16, ldc=GFD
    {
        dim3 grid(GFD / 128, DH / 128);
        gemm_wide<<<grid, 128, WIDE_SMEM>>>(GsTF, WgF, GFD, GFD / KTILE, 3, GFD,
            nullptr, nullptr, nullptr, W2TF);
    }

    // ---- side: gf conversion hidden under GEMM1 ----
    cudaStreamWaitEvent(sideS, evFork1, 0);
    csingle_h4<<<(BT * GFD / 4) / 1024, 256, 0, sideS>>>((const float4*)gf,
        (__half2*)gfF, BT * GFD / 4);
    cudaEventRecord(evJoin, sideS);

    // ---- main: join, then dependent GEMMs ----
    cudaStreamWaitEvent(0, evJoin, 0);
    // GEMM2 (wide 1-pass): g_star = gf @ W2 + b2 -> fp16 hi/lo, ldc=DH
    {
        dim3 grid(DH / 128, BT / 128);
        gemm_wide<<<grid, 128, WIDE_SMEM>>>(gfF, W2TF, GFD, GFD / KTILE, 1, DH,
            b2p, gsH, gsL, nullptr);
    }
    // GEMM3 (narrow 1-pass, fused): scores = tanh(gsH@Wgs + dec + cov) . v
    {
        dim3 grid(DH / 64, BT / 128);
        gemm_scores<<<grid, 128, SCORES_SMEM>>>(gsH, WgsTF, DH, DH / KTILE,
            decp, cov, v, scoresp);
    }
    // softmax + outputs
    softmax_kernel<<<BATCH, 256>>>(scoresp, cov, alphap, out);
    // context vector (reads fp16 hi/lo, half2-vectorized)
    {   dim3 grid(DH / 256, BATCH);  cimg_kernel<<<grid, 128>>>((const __half2*)gsH, (const __half2*)gsL, alphap, out); }
}